// round 14
// baseline (speedup 1.0000x reference)
#include <cuda_runtime.h>
#include <cstdint>

// Problem constants
#define BATCH 4
#define SEQ   2048
#define DMODEL 1024
#define NHEADS 16
#define DHEAD  64
#define MROWS (BATCH*SEQ)   // 8192

// Scratch (allocation-free: __device__ globals)
__device__ float g_q [BATCH*NHEADS*SEQ*DHEAD];   // [B,H,L,dh] tf32-rounded (+q scaled)
__device__ float g_k [BATCH*NHEADS*SEQ*DHEAD];
__device__ float g_v [BATCH*NHEADS*SEQ*DHEAD];
__device__ float g_ao[MROWS*DMODEL];             // [B*L, D] tf32-rounded
__device__ float g_xr[MROWS*DMODEL];             // tf32-rounded x
__device__ float g_wr[4*DMODEL*DMODEL];          // tf32-rounded Wq,Wk,Wv,Wo

__device__ __forceinline__ float tf32f(float f) {
    uint32_t r;
    asm("cvt.rna.tf32.f32 %0, %1;" : "=r"(r) : "f"(f));
    return __uint_as_float(r);
}

#define LDSM4(r0,r1,r2,r3,addr) \
    asm volatile("ldmatrix.sync.aligned.m8n8.x4.shared.b16 {%0,%1,%2,%3}, [%4];" \
        : "=r"(r0),"=r"(r1),"=r"(r2),"=r"(r3) : "r"(addr))

#define MMA_TF32(c,a,b0,b1) \
    asm volatile("mma.sync.aligned.m16n8k8.row.col.f32.tf32.tf32.f32 " \
        "{%0,%1,%2,%3},{%4,%5,%6,%7},{%8,%9},{%0,%1,%2,%3};" \
        : "+f"(c[0]),"+f"(c[1]),"+f"(c[2]),"+f"(c[3]) \
        : "r"(a[0]),"r"(a[1]),"r"(a[2]),"r"(a[3]),"r"(b0),"r"(b1))

#define CP16(dst,src) \
    asm volatile("cp.async.cg.shared.global [%0], [%1], 16;" \
        :: "r"(dst), "l"(src) : "memory")
#define CPCOMMIT() asm volatile("cp.async.commit_group;" ::: "memory")
#define CPWAIT(n)  asm volatile("cp.async.wait_group %0;" :: "n"(n) : "memory")

// ---------------------------------------------------------------------------
// Pre-round passes: fp32 -> tf32-rounded fp32
// ---------------------------------------------------------------------------
__global__ void __launch_bounds__(256)
round_x_kernel(const float* __restrict__ src, float* __restrict__ dst, int n4)
{
    int i = blockIdx.x * 256 + threadIdx.x;
    if (i >= n4) return;
    float4 v = reinterpret_cast<const float4*>(src)[i];
    v.x = tf32f(v.x); v.y = tf32f(v.y); v.z = tf32f(v.z); v.w = tf32f(v.w);
    reinterpret_cast<float4*>(dst)[i] = v;
}

__global__ void __launch_bounds__(256)
round_w_kernel(const float* __restrict__ Wq, const float* __restrict__ Wk,
               const float* __restrict__ Wv, const float* __restrict__ Wo,
               float* __restrict__ dst)
{
    const int z = blockIdx.y;
    const float* src = (z == 0) ? Wq : (z == 1) ? Wk : (z == 2) ? Wv : Wo;
    int i = blockIdx.x * 256 + threadIdx.x;
    float4 v = reinterpret_cast<const float4*>(src)[i];
    v.x = tf32f(v.x); v.y = tf32f(v.y); v.z = tf32f(v.z); v.w = tf32f(v.w);
    reinterpret_cast<float4*>(dst + (size_t)z * DMODEL * DMODEL)[i] = v;
}

// ---------------------------------------------------------------------------
// tf32 GEMM: C = A @ W^T, operands pre-rounded. cp.async 3-stage pipeline.
// CTA tile 128x256x32, 256 threads (8 warps, 2x4), warp tile 64x64.
// Stage = A[128*36] + W[256*36] = 13824 fl = 55296 B; 3 stages = 165888 B.
// 1 CTA/SM, but 8 warps in-CTA keep all 4 SMSPs double-subscribed.
// ---------------------------------------------------------------------------
#define GAW   4608                    // A region floats (128*36)
#define GSTF  13824                   // stage floats (A + W[256*36])
#define GEMM_SMEM_BYTES (3*GSTF*4)    // 165888

__device__ __forceinline__ void gemm_load_stage(
    const float* __restrict__ A, const float* __restrict__ W,
    int m0, int n0, int k0, uint32_t sb, int tid)
{
    #pragma unroll
    for (int it = 0; it < 4; it++) {            // A: 128 rows x 8 cg
        int idx = tid + it * 256;
        int row = idx >> 3, cg = idx & 7;
        CP16(sb + (uint32_t)((row*36 + cg*4) * 4),
             (const void*)&A[(size_t)(m0 + row) * DMODEL + k0 + cg*4]);
    }
    #pragma unroll
    for (int it = 0; it < 8; it++) {            // W: 256 rows x 8 cg
        int idx = tid + it * 256;
        int row = idx >> 3, cg = idx & 7;
        CP16(sb + (uint32_t)((GAW + row*36 + cg*4) * 4),
             (const void*)&W[(size_t)(n0 + row) * DMODEL + k0 + cg*4]);
    }
}

template<int PERMUTE, int ROUND>
__device__ __forceinline__ void gemm_core(
    const float* __restrict__ A, const float* __restrict__ W,
    float* __restrict__ C, float scale)
{
    extern __shared__ float sm[];
    const int tid  = threadIdx.x;
    const int lane = tid & 31;
    const int wid  = tid >> 5;         // 0..7
    const int m0 = blockIdx.y * 128;
    const int n0 = blockIdx.x * 256;
    const int wm = (wid & 1) * 64;     // 2 warps over M
    const int wn = (wid >> 1) * 64;    // 4 warps over N

    float c[4][8][4];
    #pragma unroll
    for (int i = 0; i < 4; i++)
        #pragma unroll
        for (int j = 0; j < 8; j++)
            #pragma unroll
            for (int r = 0; r < 4; r++) c[i][j][r] = 0.0f;

    uint32_t sb = (uint32_t)__cvta_generic_to_shared(sm);
    uint32_t a_addr[4], b_addr[4];
    #pragma unroll
    for (int i = 0; i < 4; i++)
        a_addr[i] = sb + ((wm + i*16 + (lane & 15)) * 36 + (lane >> 4) * 4) * 4;
    #pragma unroll
    for (int p = 0; p < 4; p++)
        b_addr[p] = sb + (GAW +
            (wn + p*16 + ((lane >> 4) & 1) * 8 + (lane & 7)) * 36
            + ((lane >> 3) & 1) * 4) * 4;

    const int NK = DMODEL / 32;   // 32 k-slabs

    gemm_load_stage(A, W, m0, n0, 0,  sb,            tid); CPCOMMIT();
    gemm_load_stage(A, W, m0, n0, 32, sb + GSTF*4,   tid); CPCOMMIT();
    gemm_load_stage(A, W, m0, n0, 64, sb + 2*GSTF*4, tid); CPCOMMIT();

    #pragma unroll 1
    for (int i = 0; i < NK; i++) {
        CPWAIT(2);          // stage i complete
        __syncthreads();

        const uint32_t soff = (uint32_t)(i % 3) * (GSTF*4);
        #pragma unroll
        for (int s = 0; s < 4; s++) {
            uint32_t a[4][4], bb[4][4];
            #pragma unroll
            for (int ii = 0; ii < 4; ii++)
                LDSM4(a[ii][0], a[ii][1], a[ii][2], a[ii][3],
                      a_addr[ii] + soff + s*32);
            #pragma unroll
            for (int p = 0; p < 4; p++)
                LDSM4(bb[p][0], bb[p][1], bb[p][2], bb[p][3],
                      b_addr[p] + soff + s*32);
            #pragma unroll
            for (int ii = 0; ii < 4; ii++)
                #pragma unroll
                for (int p = 0; p < 4; p++) {
                    MMA_TF32(c[ii][2*p],   a[ii], bb[p][0], bb[p][1]);
                    MMA_TF32(c[ii][2*p+1], a[ii], bb[p][2], bb[p][3]);
                }
        }
        __syncthreads();    // all reads of stage i%3 done
        if (i + 3 < NK)
            gemm_load_stage(A, W, m0, n0, (i+3)*32, sb + soff, tid);
        CPCOMMIT();
    }

    // Epilogue
    const int g  = lane >> 2;
    const int tq = lane & 3;
    #pragma unroll
    for (int i = 0; i < 4; i++) {
        #pragma unroll
        for (int j = 0; j < 8; j++) {
            int col = n0 + wn + j*8 + tq*2;
            #pragma unroll
            for (int t = 0; t < 2; t++) {
                int row = m0 + wm + i*16 + g + t*8;
                float v0 = c[i][j][2*t], v1 = c[i][j][2*t+1];
                if (ROUND) { v0 = tf32f(v0 * scale); v1 = tf32f(v1 * scale); }
                float2 v = make_float2(v0, v1);
                if (PERMUTE) {
                    int b = row >> 11, l = row & (SEQ - 1);
                    int h = col >> 6, d = col & 63;
                    *reinterpret_cast<float2*>(
                        &C[(((size_t)(b*NHEADS + h)) * SEQ + l) * DHEAD + d]) = v;
                } else {
                    *reinterpret_cast<float2*>(&C[(size_t)row * DMODEL + col]) = v;
                }
            }
        }
    }
}

__global__ void __launch_bounds__(256, 1)
gemm_qkv_kernel(const float* __restrict__ xr, const float* __restrict__ wr,
                float* __restrict__ q, float* __restrict__ k,
                float* __restrict__ v)
{
    const int z = blockIdx.z;
    const float* W = wr + (size_t)z * DMODEL * DMODEL;
    float* C = (z == 0) ? q : (z == 1) ? k : v;
    float scale = (z == 0) ? 0.125f : 1.0f;
    gemm_core<1, 1>(xr, W, C, scale);
}

__global__ void __launch_bounds__(256, 1)
gemm_o_kernel(const float* __restrict__ ao, const float* __restrict__ wr,
              float* __restrict__ out)
{
    gemm_core<0, 0>(ao, wr + (size_t)3 * DMODEL * DMODEL, out, 1.0f);
}

// ---------------------------------------------------------------------------
// Flash attention, tf32 mma (round 13 — current best, unchanged).
// CTA = 128 q x (b,h), 128 threads, 4 warps, warp tile m32 x n64, BK=64.
// Single-buffered K/V, padded stride 68; pair-coalesced V gather.
// smem floats: Qs[128*68] | Ps[128*68] | Ks[64*68] | Vt[64*68] = 104448 B
// ---------------------------------------------------------------------------
#define AQS 0
#define APS 8704
#define AKS 17408
#define AVT 21760
#define ATTN_SMEM_BYTES (26112*4)   // 104448

__global__ void __launch_bounds__(128, 2)
attn_tf32(const float* __restrict__ gq, const float* __restrict__ gk,
          const float* __restrict__ gv, float* __restrict__ ao)
{
    extern __shared__ float sm[];
    float* Ps  = sm + APS;
    float* Vts = sm + AVT;

    const int tid  = threadIdx.x;
    const int lane = tid & 31;
    const int wid  = tid >> 5;                    // 0..3, owns 32 q rows
    const int bh = blockIdx.y;
    const int q0 = ((int)gridDim.x - 1 - (int)blockIdx.x) * 128;  // heavy first

    uint32_t smb  = (uint32_t)__cvta_generic_to_shared(sm);
    uint32_t qs_b = smb + AQS*4;
    uint32_t ps_b = smb + APS*4;
    uint32_t ks_b = smb + AKS*4;
    uint32_t vt_b = smb + AVT*4;

    const float4* qbase = reinterpret_cast<const float4*>(
        gq + ((size_t)bh * SEQ + q0) * DHEAD);
    const float* kko = gk + (size_t)bh * SEQ * DHEAD;
    const float4* vvo = reinterpret_cast<const float4*>(
        gv + (size_t)bh * SEQ * DHEAD);

    // Prologue: cp.async Q + K0, pair-coalesced transpose-gather V0
    #pragma unroll
    for (int it = 0; it < 16; it++) {
        int idx = tid + it * 128;
        int row = idx >> 4, cg = idx & 15;
        CP16(qs_b + (uint32_t)((row*68 + cg*4) * 4), (const void*)(qbase + idx));
    }
    #pragma unroll
    for (int it = 0; it < 8; it++) {
        int idx = tid + it * 128;
        int row = idx >> 4, cg = idx & 15;
        CP16(ks_b + (uint32_t)((row*68 + cg*4) * 4),
             (const void*)(kko + (size_t)row * DHEAD + cg*4));
    }
    CPCOMMIT();
    float4 ra[8];
    #pragma unroll
    for (int it = 0; it < 8; it++) {
        int idx = tid + it * 128;
        int r  = (idx >> 1) & 63;
        int cg = ((idx >> 6) & 14) | (idx & 1);
        ra[it] = vvo[r * 16 + cg];                // V[r][cg*4..+3]
    }

    // LDSM addresses
    uint32_t qa_addr[2], pa_addr[2];
    #pragma unroll
    for (int mi = 0; mi < 2; mi++) {
        uint32_t roff = ((wid*32 + mi*16 + (lane & 15)) * 68 + (lane >> 4) * 4) * 4;
        qa_addr[mi] = qs_b + roff;
        pa_addr[mi] = ps_b + roff;
    }
    uint32_t kb_addr[4], vb_addr[4];
    #pragma unroll
    for (int p = 0; p < 4; p++) {
        uint32_t roff = ((p*16 + ((lane >> 4) & 1) * 8 + (lane & 7)) * 68
                        + ((lane >> 3) & 1) * 4) * 4;
        kb_addr[p] = ks_b + roff;
        vb_addr[p] = vt_b + roff;
    }

    float m_i[2][2] = {{-1e30f, -1e30f}, {-1e30f, -1e30f}};
    float l_i[2][2] = {{0.0f, 0.0f}, {0.0f, 0.0f}};
    float o[2][8][4];
    #pragma unroll
    for (int mi = 0; mi < 2; mi++)
        #pragma unroll
        for (int j = 0; j < 8; j++)
            #pragma unroll
            for (int r = 0; r < 4; r++) o[mi][j][r] = 0.0f;

    const int g  = lane >> 2;
    const int tq = lane & 3;

    const int nkb = (q0 + 128) / 64;
    #pragma unroll 1
    for (int kb = 0; kb < nkb; kb++) {
        if (kb > 0) {
            __syncthreads();   // prev iter's K/V smem reads complete
            const float* knxt = kko + (size_t)kb * 64 * DHEAD;
            #pragma unroll
            for (int it = 0; it < 8; it++) {
                int idx = tid + it * 128;
                int row = idx >> 4, cg = idx & 15;
                CP16(ks_b + (uint32_t)((row*68 + cg*4) * 4),
                     (const void*)(knxt + (size_t)row * DHEAD + cg*4));
            }
            CPCOMMIT();
        }
        // Store prefetched V[kb] transposed into Vt (conflict-free pattern)
        #pragma unroll
        for (int it = 0; it < 8; it++) {
            int idx = tid + it * 128;
            int r  = (idx >> 1) & 63;
            int cg = ((idx >> 6) & 14) | (idx & 1);
            Vts[(cg*4+0) * 68 + r] = ra[it].x;
            Vts[(cg*4+1) * 68 + r] = ra[it].y;
            Vts[(cg*4+2) * 68 + r] = ra[it].z;
            Vts[(cg*4+3) * 68 + r] = ra[it].w;
        }
        CPWAIT(0);
        __syncthreads();

        // S = Q @ K^T : warp m32 x n64 x k64
        float sf[2][8][4];
        #pragma unroll
        for (int mi = 0; mi < 2; mi++)
            #pragma unroll
            for (int j = 0; j < 8; j++)
                #pragma unroll
                for (int r = 0; r < 4; r++) sf[mi][j][r] = 0.0f;

        #pragma unroll
        for (int s = 0; s < 8; s++) {
            uint32_t a[2][4], bb[4][4];
            #pragma unroll
            for (int mi = 0; mi < 2; mi++)
                LDSM4(a[mi][0], a[mi][1], a[mi][2], a[mi][3], qa_addr[mi] + s*32);
            #pragma unroll
            for (int p = 0; p < 4; p++)
                LDSM4(bb[p][0], bb[p][1], bb[p][2], bb[p][3], kb_addr[p] + s*32);
            #pragma unroll
            for (int mi = 0; mi < 2; mi++)
                #pragma unroll
                for (int p = 0; p < 4; p++) {
                    MMA_TF32(sf[mi][2*p],   a[mi], bb[p][0], bb[p][1]);
                    MMA_TF32(sf[mi][2*p+1], a[mi], bb[p][2], bb[p][3]);
                }
        }

        // Causal mask (near diagonal only)
        const int k0 = kb * 64;
        if (k0 + 63 > q0 + wid*32) {
            #pragma unroll
            for (int mi = 0; mi < 2; mi++)
                #pragma unroll
                for (int t = 0; t < 2; t++) {
                    int qg = q0 + wid*32 + mi*16 + g + t*8;
                    #pragma unroll
                    for (int j = 0; j < 8; j++) {
                        int kg = k0 + j*8 + tq*2;
                        if (kg   > qg) sf[mi][j][2*t]   = -1e30f;
                        if (kg+1 > qg) sf[mi][j][2*t+1] = -1e30f;
                    }
                }
        }

        // Online softmax; write P (tf32) to warp-private Ps rows
        #pragma unroll
        for (int mi = 0; mi < 2; mi++)
            #pragma unroll
            for (int t = 0; t < 2; t++) {
                float mx = -1e30f;
                #pragma unroll
                for (int j = 0; j < 8; j++)
                    mx = fmaxf(mx, fmaxf(sf[mi][j][2*t], sf[mi][j][2*t+1]));
                mx = fmaxf(mx, __shfl_xor_sync(0xffffffffu, mx, 1));
                mx = fmaxf(mx, __shfl_xor_sync(0xffffffffu, mx, 2));
                float newm = fmaxf(m_i[mi][t], mx);
                float corr = __expf(m_i[mi][t] - newm);
                float rs = 0.0f;
                int prow = (wid*32 + mi*16 + g + t*8) * 68 + tq*2;
                #pragma unroll
                for (int j = 0; j < 8; j++) {
                    float p0 = __expf(sf[mi][j][2*t]   - newm);
                    float p1 = __expf(sf[mi][j][2*t+1] - newm);
                    rs += p0 + p1;
                    *reinterpret_cast<float2*>(&Ps[prow + j*8]) =
                        make_float2(tf32f(p0), tf32f(p1));
                }
                rs += __shfl_xor_sync(0xffffffffu, rs, 1);
                rs += __shfl_xor_sync(0xffffffffu, rs, 2);
                l_i[mi][t] = l_i[mi][t] * corr + rs;
                m_i[mi][t] = newm;
                #pragma unroll
                for (int j = 0; j < 8; j++) {
                    o[mi][j][2*t]   *= corr;
                    o[mi][j][2*t+1] *= corr;
                }
            }
        __syncwarp();

        // Prefetch V[kb+1] (pair-coalesced gather; latency hidden by PV mma)
        if (kb + 1 < nkb) {
            const float4* vnxt = vvo + (size_t)(kb+1) * 64 * DHEAD / 4;
            #pragma unroll
            for (int it = 0; it < 8; it++) {
                int idx = tid + it * 128;
                int r  = (idx >> 1) & 63;
                int cg = ((idx >> 6) & 14) | (idx & 1);
                ra[it] = vnxt[r * 16 + cg];
            }
        }

        // O += P @ V : warp m32(q) x n64(d) x k64(keys)
        #pragma unroll
        for (int s = 0; s < 8; s++) {
            uint32_t a[2][4], bb[4][4];
            #pragma unroll
            for (int mi = 0; mi < 2; mi++)
                LDSM4(a[mi][0], a[mi][1], a[mi][2], a[mi][3], pa_addr[mi] + s*32);
            #pragma unroll
            for (int p = 0; p < 4; p++)
                LDSM4(bb[p][0], bb[p][1], bb[p][2], bb[p][3], vb_addr[p] + s*32);
            #pragma unroll
            for (int mi = 0; mi < 2; mi++)
                #pragma unroll
                for (int p = 0; p < 4; p++) {
                    MMA_TF32(o[mi][2*p],   a[mi], bb[p][0], bb[p][1]);
                    MMA_TF32(o[mi][2*p+1], a[mi], bb[p][2], bb[p][3]);
                }
        }
    }

    // Normalize and write tf32-rounded to [B*L, D] (col = h*64 + d)
    const int b = bh >> 4;
    const int h = bh & 15;
    #pragma unroll
    for (int mi = 0; mi < 2; mi++)
        #pragma unroll
        for (int t = 0; t < 2; t++) {
            float inv = 1.0f / l_i[mi][t];
            int row = q0 + wid*32 + mi*16 + g + t*8;
            float* dst = ao + ((size_t)(b * SEQ + row)) * DMODEL + h * DHEAD + tq*2;
            #pragma unroll
            for (int j = 0; j < 8; j++)
                *reinterpret_cast<float2*>(dst + j*8) =
                    make_float2(tf32f(o[mi][j][2*t] * inv),
                                tf32f(o[mi][j][2*t+1] * inv));
        }
}

// ---------------------------------------------------------------------------
extern "C" void kernel_launch(void* const* d_in, const int* in_sizes, int n_in,
                              void* d_out, int out_size)
{
    const float* x  = (const float*)d_in[0];
    const float* Wq = (const float*)d_in[1];
    const float* Wk = (const float*)d_in[2];
    const float* Wv = (const float*)d_in[3];
    const float* Wo = (const float*)d_in[4];
    float* out = (float*)d_out;

    float *qp, *kp, *vp, *aop, *xrp, *wrp;
    cudaGetSymbolAddress((void**)&qp,  g_q);
    cudaGetSymbolAddress((void**)&kp,  g_k);
    cudaGetSymbolAddress((void**)&vp,  g_v);
    cudaGetSymbolAddress((void**)&aop, g_ao);
    cudaGetSymbolAddress((void**)&xrp, g_xr);
    cudaGetSymbolAddress((void**)&wrp, g_wr);

    cudaFuncSetAttribute(gemm_qkv_kernel,
        cudaFuncAttributeMaxDynamicSharedMemorySize, GEMM_SMEM_BYTES);
    cudaFuncSetAttribute(gemm_o_kernel,
        cudaFuncAttributeMaxDynamicSharedMemorySize, GEMM_SMEM_BYTES);
    cudaFuncSetAttribute(attn_tf32,
        cudaFuncAttributeMaxDynamicSharedMemorySize, ATTN_SMEM_BYTES);

    const int n4x = MROWS * DMODEL / 4;
    const int n4w = DMODEL * DMODEL / 4;
    round_x_kernel<<<n4x/256, 256>>>(x, xrp, n4x);
    dim3 wgrid(n4w/256, 4);
    round_w_kernel<<<wgrid, 256>>>(Wq, Wk, Wv, Wo, wrp);

    dim3 qkv_grid(DMODEL/256, MROWS/128, 3);   // (4, 64, 3) = 768 CTAs
    gemm_qkv_kernel<<<qkv_grid, 256, GEMM_SMEM_BYTES>>>(xrp, wrp, qp, kp, vp);

    dim3 attn_grid(SEQ/128, BATCH*NHEADS);     // (16, 64)
    attn_tf32<<<attn_grid, 128, ATTN_SMEM_BYTES>>>(qp, kp, vp, aop);

    dim3 o_grid(DMODEL/256, MROWS/128);        // (4, 64) = 256 CTAs
    gemm_o_kernel<<<o_grid, 256, GEMM_SMEM_BYTES>>>(aop, wrp, out);
}

// round 15
// speedup vs baseline: 1.0866x; 1.0866x over previous
#include <cuda_runtime.h>
#include <cstdint>

// Problem constants
#define BATCH 4
#define SEQ   2048
#define DMODEL 1024
#define NHEADS 16
#define DHEAD  64
#define MROWS (BATCH*SEQ)   // 8192

// Scratch (allocation-free: __device__ globals)
__device__ float g_q [BATCH*NHEADS*SEQ*DHEAD];   // [B,H,L,dh] tf32-rounded (+q scaled)
__device__ float g_k [BATCH*NHEADS*SEQ*DHEAD];
__device__ float g_v [BATCH*NHEADS*SEQ*DHEAD];
__device__ float g_ao[MROWS*DMODEL];             // [B*L, D] tf32-rounded
__device__ float g_xr[MROWS*DMODEL];             // tf32-rounded x
__device__ float g_wr[4*DMODEL*DMODEL];          // tf32-rounded Wq,Wk,Wv,Wo

__device__ __forceinline__ float tf32f(float f) {
    uint32_t r;
    asm("cvt.rna.tf32.f32 %0, %1;" : "=r"(r) : "f"(f));
    return __uint_as_float(r);
}

#define LDSM4(r0,r1,r2,r3,addr) \
    asm volatile("ldmatrix.sync.aligned.m8n8.x4.shared.b16 {%0,%1,%2,%3}, [%4];" \
        : "=r"(r0),"=r"(r1),"=r"(r2),"=r"(r3) : "r"(addr))

#define MMA_TF32(c,a,b0,b1) \
    asm volatile("mma.sync.aligned.m16n8k8.row.col.f32.tf32.tf32.f32 " \
        "{%0,%1,%2,%3},{%4,%5,%6,%7},{%8,%9},{%0,%1,%2,%3};" \
        : "+f"(c[0]),"+f"(c[1]),"+f"(c[2]),"+f"(c[3]) \
        : "r"(a[0]),"r"(a[1]),"r"(a[2]),"r"(a[3]),"r"(b0),"r"(b1))

#define CP16(dst,src) \
    asm volatile("cp.async.cg.shared.global [%0], [%1], 16;" \
        :: "r"(dst), "l"(src) : "memory")
#define CPCOMMIT() asm volatile("cp.async.commit_group;" ::: "memory")
#define CPWAIT(n)  asm volatile("cp.async.wait_group %0;" :: "n"(n) : "memory")

// ---------------------------------------------------------------------------
// Merged pre-round pass: x (2^21 f4) then Wq,Wk,Wv,Wo (4 x 2^18 f4)
// ---------------------------------------------------------------------------
#define N4X  (MROWS*DMODEL/4)          // 2097152 = 2^21
#define N4W  (DMODEL*DMODEL/4)         // 262144  = 2^18
#define ROUND_BLOCKS ((N4X + 4*N4W)/256)

__global__ void __launch_bounds__(256)
round_all_kernel(const float* __restrict__ x,
                 const float* __restrict__ Wq, const float* __restrict__ Wk,
                 const float* __restrict__ Wv, const float* __restrict__ Wo,
                 float* __restrict__ xr, float* __restrict__ wr)
{
    int i = blockIdx.x * 256 + threadIdx.x;
    const float* src;
    float* dst;
    if (i < N4X) {
        src = x; dst = xr;
    } else {
        int j = i - N4X;
        int z = j >> 18;
        i = j & (N4W - 1);
        src = (z == 0) ? Wq : (z == 1) ? Wk : (z == 2) ? Wv : Wo;
        dst = wr + (size_t)z * DMODEL * DMODEL;
    }
    float4 v = reinterpret_cast<const float4*>(src)[i];
    v.x = tf32f(v.x); v.y = tf32f(v.y); v.z = tf32f(v.z); v.w = tf32f(v.w);
    reinterpret_cast<float4*>(dst)[i] = v;
}

// ---------------------------------------------------------------------------
// tf32 GEMM (round 13 config — best known): cp.async 3-stage pipeline.
// CTA 128x128x32, 256 threads (8 warps 2x4), warp tile 64x32, 2 CTAs/SM.
// ---------------------------------------------------------------------------
#define GSTF  9216
#define GWOFF 4608
#define GEMM_SMEM_BYTES (3*GSTF*4)   // 110592

__device__ __forceinline__ void gemm_load_stage(
    const float* __restrict__ A, const float* __restrict__ W,
    int m0, int n0, int k0, uint32_t sb, int tid)
{
    #pragma unroll
    for (int it = 0; it < 4; it++) {
        int idx = tid + it * 256;
        int row = idx >> 3, cg = idx & 7;
        CP16(sb + (uint32_t)((row*36 + cg*4) * 4),
             (const void*)&A[(size_t)(m0 + row) * DMODEL + k0 + cg*4]);
        CP16(sb + (uint32_t)((GWOFF + row*36 + cg*4) * 4),
             (const void*)&W[(size_t)(n0 + row) * DMODEL + k0 + cg*4]);
    }
}

template<int PERMUTE, int ROUND>
__device__ __forceinline__ void gemm_core(
    const float* __restrict__ A, const float* __restrict__ W,
    float* __restrict__ C, float scale)
{
    extern __shared__ float sm[];
    const int tid  = threadIdx.x;
    const int lane = tid & 31;
    const int wid  = tid >> 5;
    const int m0 = blockIdx.y * 128;
    const int n0 = blockIdx.x * 128;
    const int wm = (wid & 1) * 64;
    const int wn = (wid >> 1) * 32;

    float c[4][4][4];
    #pragma unroll
    for (int i = 0; i < 4; i++)
        #pragma unroll
        for (int j = 0; j < 4; j++)
            #pragma unroll
            for (int r = 0; r < 4; r++) c[i][j][r] = 0.0f;

    uint32_t sb = (uint32_t)__cvta_generic_to_shared(sm);
    uint32_t a_addr[4], b_addr[2];
    #pragma unroll
    for (int i = 0; i < 4; i++)
        a_addr[i] = sb + ((wm + i*16 + (lane & 15)) * 36 + (lane >> 4) * 4) * 4;
    #pragma unroll
    for (int p = 0; p < 2; p++)
        b_addr[p] = sb + (GWOFF +
            (wn + p*16 + ((lane >> 4) & 1) * 8 + (lane & 7)) * 36
            + ((lane >> 3) & 1) * 4) * 4;

    const int NK = DMODEL / 32;

    gemm_load_stage(A, W, m0, n0, 0,  sb,            tid); CPCOMMIT();
    gemm_load_stage(A, W, m0, n0, 32, sb + GSTF*4,   tid); CPCOMMIT();
    gemm_load_stage(A, W, m0, n0, 64, sb + 2*GSTF*4, tid); CPCOMMIT();

    #pragma unroll 1
    for (int i = 0; i < NK; i++) {
        CPWAIT(2);
        __syncthreads();

        const uint32_t soff = (uint32_t)(i % 3) * (GSTF*4);
        #pragma unroll
        for (int s = 0; s < 4; s++) {
            uint32_t a[4][4], bb[2][4];
            #pragma unroll
            for (int ii = 0; ii < 4; ii++)
                LDSM4(a[ii][0], a[ii][1], a[ii][2], a[ii][3],
                      a_addr[ii] + soff + s*32);
            #pragma unroll
            for (int p = 0; p < 2; p++)
                LDSM4(bb[p][0], bb[p][1], bb[p][2], bb[p][3],
                      b_addr[p] + soff + s*32);
            #pragma unroll
            for (int ii = 0; ii < 4; ii++) {
                MMA_TF32(c[ii][0], a[ii], bb[0][0], bb[0][1]);
                MMA_TF32(c[ii][1], a[ii], bb[0][2], bb[0][3]);
                MMA_TF32(c[ii][2], a[ii], bb[1][0], bb[1][1]);
                MMA_TF32(c[ii][3], a[ii], bb[1][2], bb[1][3]);
            }
        }
        __syncthreads();
        if (i + 3 < NK)
            gemm_load_stage(A, W, m0, n0, (i+3)*32, sb + soff, tid);
        CPCOMMIT();
    }

    const int g  = lane >> 2;
    const int tq = lane & 3;
    #pragma unroll
    for (int i = 0; i < 4; i++) {
        #pragma unroll
        for (int j = 0; j < 4; j++) {
            int col = n0 + wn + j*8 + tq*2;
            #pragma unroll
            for (int t = 0; t < 2; t++) {
                int row = m0 + wm + i*16 + g + t*8;
                float v0 = c[i][j][2*t], v1 = c[i][j][2*t+1];
                if (ROUND) { v0 = tf32f(v0 * scale); v1 = tf32f(v1 * scale); }
                float2 v = make_float2(v0, v1);
                if (PERMUTE) {
                    int b = row >> 11, l = row & (SEQ - 1);
                    int h = col >> 6, d = col & 63;
                    *reinterpret_cast<float2*>(
                        &C[(((size_t)(b*NHEADS + h)) * SEQ + l) * DHEAD + d]) = v;
                } else {
                    *reinterpret_cast<float2*>(&C[(size_t)row * DMODEL + col]) = v;
                }
            }
        }
    }
}

__global__ void __launch_bounds__(256, 2)
gemm_qkv_kernel(const float* __restrict__ xr, const float* __restrict__ wr,
                float* __restrict__ q, float* __restrict__ k,
                float* __restrict__ v)
{
    const int z = blockIdx.z;
    const float* W = wr + (size_t)z * DMODEL * DMODEL;
    float* C = (z == 0) ? q : (z == 1) ? k : v;
    float scale = (z == 0) ? 0.125f : 1.0f;
    gemm_core<1, 1>(xr, W, C, scale);
}

__global__ void __launch_bounds__(256, 2)
gemm_o_kernel(const float* __restrict__ ao, const float* __restrict__ wr,
              float* __restrict__ out)
{
    gemm_core<0, 0>(ao, wr + (size_t)3 * DMODEL * DMODEL, out, 1.0f);
}

// ---------------------------------------------------------------------------
// Flash attention, tf32 mma (round 13 base + softmax/PV interleave).
// CTA = 128 q x (b,h), 128 threads, 4 warps, warp tile m32 x n64, BK=64.
// Single-buffered K/V, padded stride 68; pair-coalesced V gather.
// NEW: exp+store of P group s+1 overlaps LDSM+MMA of group s (bit-identical).
// smem floats: Qs[128*68] | Ps[128*68] | Ks[64*68] | Vt[64*68] = 104448 B
// ---------------------------------------------------------------------------
#define AQS 0
#define APS 8704
#define AKS 17408
#define AVT 21760
#define ATTN_SMEM_BYTES (26112*4)   // 104448

__global__ void __launch_bounds__(128, 2)
attn_tf32(const float* __restrict__ gq, const float* __restrict__ gk,
          const float* __restrict__ gv, float* __restrict__ ao)
{
    extern __shared__ float sm[];
    float* Ps  = sm + APS;
    float* Vts = sm + AVT;

    const int tid  = threadIdx.x;
    const int lane = tid & 31;
    const int wid  = tid >> 5;                    // 0..3, owns 32 q rows
    const int bh = blockIdx.y;
    const int q0 = ((int)gridDim.x - 1 - (int)blockIdx.x) * 128;  // heavy first

    uint32_t smb  = (uint32_t)__cvta_generic_to_shared(sm);
    uint32_t qs_b = smb + AQS*4;
    uint32_t ps_b = smb + APS*4;
    uint32_t ks_b = smb + AKS*4;
    uint32_t vt_b = smb + AVT*4;

    const float4* qbase = reinterpret_cast<const float4*>(
        gq + ((size_t)bh * SEQ + q0) * DHEAD);
    const float* kko = gk + (size_t)bh * SEQ * DHEAD;
    const float4* vvo = reinterpret_cast<const float4*>(
        gv + (size_t)bh * SEQ * DHEAD);

    // Prologue: cp.async Q + K0, pair-coalesced transpose-gather V0
    #pragma unroll
    for (int it = 0; it < 16; it++) {
        int idx = tid + it * 128;
        int row = idx >> 4, cg = idx & 15;
        CP16(qs_b + (uint32_t)((row*68 + cg*4) * 4), (const void*)(qbase + idx));
    }
    #pragma unroll
    for (int it = 0; it < 8; it++) {
        int idx = tid + it * 128;
        int row = idx >> 4, cg = idx & 15;
        CP16(ks_b + (uint32_t)((row*68 + cg*4) * 4),
             (const void*)(kko + (size_t)row * DHEAD + cg*4));
    }
    CPCOMMIT();
    float4 ra[8];
    #pragma unroll
    for (int it = 0; it < 8; it++) {
        int idx = tid + it * 128;
        int r  = (idx >> 1) & 63;
        int cg = ((idx >> 6) & 14) | (idx & 1);
        ra[it] = vvo[r * 16 + cg];                // V[r][cg*4..+3]
    }

    // LDSM addresses
    uint32_t qa_addr[2], pa_addr[2];
    #pragma unroll
    for (int mi = 0; mi < 2; mi++) {
        uint32_t roff = ((wid*32 + mi*16 + (lane & 15)) * 68 + (lane >> 4) * 4) * 4;
        qa_addr[mi] = qs_b + roff;
        pa_addr[mi] = ps_b + roff;
    }
    uint32_t kb_addr[4], vb_addr[4];
    #pragma unroll
    for (int p = 0; p < 4; p++) {
        uint32_t roff = ((p*16 + ((lane >> 4) & 1) * 8 + (lane & 7)) * 68
                        + ((lane >> 3) & 1) * 4) * 4;
        kb_addr[p] = ks_b + roff;
        vb_addr[p] = vt_b + roff;
    }

    float m_i[2][2] = {{-1e30f, -1e30f}, {-1e30f, -1e30f}};
    float l_i[2][2] = {{0.0f, 0.0f}, {0.0f, 0.0f}};
    float o[2][8][4];
    #pragma unroll
    for (int mi = 0; mi < 2; mi++)
        #pragma unroll
        for (int j = 0; j < 8; j++)
            #pragma unroll
            for (int r = 0; r < 4; r++) o[mi][j][r] = 0.0f;

    const int g  = lane >> 2;
    const int tq = lane & 3;
    int pbase[2][2];
    #pragma unroll
    for (int mi = 0; mi < 2; mi++)
        #pragma unroll
        for (int t = 0; t < 2; t++)
            pbase[mi][t] = (wid*32 + mi*16 + g + t*8) * 68 + tq*2;

    const int nkb = (q0 + 128) / 64;
    #pragma unroll 1
    for (int kb = 0; kb < nkb; kb++) {
        if (kb > 0) {
            __syncthreads();   // prev iter's K/V smem reads complete
            const float* knxt = kko + (size_t)kb * 64 * DHEAD;
            #pragma unroll
            for (int it = 0; it < 8; it++) {
                int idx = tid + it * 128;
                int row = idx >> 4, cg = idx & 15;
                CP16(ks_b + (uint32_t)((row*68 + cg*4) * 4),
                     (const void*)(knxt + (size_t)row * DHEAD + cg*4));
            }
            CPCOMMIT();
        }
        // Store prefetched V[kb] transposed into Vt (conflict-free pattern)
        #pragma unroll
        for (int it = 0; it < 8; it++) {
            int idx = tid + it * 128;
            int r  = (idx >> 1) & 63;
            int cg = ((idx >> 6) & 14) | (idx & 1);
            Vts[(cg*4+0) * 68 + r] = ra[it].x;
            Vts[(cg*4+1) * 68 + r] = ra[it].y;
            Vts[(cg*4+2) * 68 + r] = ra[it].z;
            Vts[(cg*4+3) * 68 + r] = ra[it].w;
        }
        CPWAIT(0);
        __syncthreads();

        // S = Q @ K^T : warp m32 x n64 x k64
        float sf[2][8][4];
        #pragma unroll
        for (int mi = 0; mi < 2; mi++)
            #pragma unroll
            for (int j = 0; j < 8; j++)
                #pragma unroll
                for (int r = 0; r < 4; r++) sf[mi][j][r] = 0.0f;

        #pragma unroll
        for (int s = 0; s < 8; s++) {
            uint32_t a[2][4], bb[4][4];
            #pragma unroll
            for (int mi = 0; mi < 2; mi++)
                LDSM4(a[mi][0], a[mi][1], a[mi][2], a[mi][3], qa_addr[mi] + s*32);
            #pragma unroll
            for (int p = 0; p < 4; p++)
                LDSM4(bb[p][0], bb[p][1], bb[p][2], bb[p][3], kb_addr[p] + s*32);
            #pragma unroll
            for (int mi = 0; mi < 2; mi++)
                #pragma unroll
                for (int p = 0; p < 4; p++) {
                    MMA_TF32(sf[mi][2*p],   a[mi], bb[p][0], bb[p][1]);
                    MMA_TF32(sf[mi][2*p+1], a[mi], bb[p][2], bb[p][3]);
                }
        }

        // Causal mask (near diagonal only)
        const int k0 = kb * 64;
        if (k0 + 63 > q0 + wid*32) {
            #pragma unroll
            for (int mi = 0; mi < 2; mi++)
                #pragma unroll
                for (int t = 0; t < 2; t++) {
                    int qg = q0 + wid*32 + mi*16 + g + t*8;
                    #pragma unroll
                    for (int j = 0; j < 8; j++) {
                        int kg = k0 + j*8 + tq*2;
                        if (kg   > qg) sf[mi][j][2*t]   = -1e30f;
                        if (kg+1 > qg) sf[mi][j][2*t+1] = -1e30f;
                    }
                }
        }

        // Softmax phase 1: row max, corr, o-scale (m_i <- newm)
        float corr2[2][2], rsv[2][2];
        #pragma unroll
        for (int mi = 0; mi < 2; mi++)
            #pragma unroll
            for (int t = 0; t < 2; t++) {
                float mx = -1e30f;
                #pragma unroll
                for (int j = 0; j < 8; j++)
                    mx = fmaxf(mx, fmaxf(sf[mi][j][2*t], sf[mi][j][2*t+1]));
                mx = fmaxf(mx, __shfl_xor_sync(0xffffffffu, mx, 1));
                mx = fmaxf(mx, __shfl_xor_sync(0xffffffffu, mx, 2));
                float newm = fmaxf(m_i[mi][t], mx);
                corr2[mi][t] = __expf(m_i[mi][t] - newm);
                m_i[mi][t] = newm;
                rsv[mi][t] = 0.0f;
                #pragma unroll
                for (int j = 0; j < 8; j++) {
                    o[mi][j][2*t]   *= corr2[mi][t];
                    o[mi][j][2*t+1] *= corr2[mi][t];
                }
            }

        // exp+store helper (group jj)
        auto exp_store = [&](int jj) {
            #pragma unroll
            for (int mi = 0; mi < 2; mi++)
                #pragma unroll
                for (int t = 0; t < 2; t++) {
                    float p0 = __expf(sf[mi][jj][2*t]   - m_i[mi][t]);
                    float p1 = __expf(sf[mi][jj][2*t+1] - m_i[mi][t]);
                    rsv[mi][t] += p0 + p1;
                    *reinterpret_cast<float2*>(&Ps[pbase[mi][t] + jj*8]) =
                        make_float2(tf32f(p0), tf32f(p1));
                }
        };
        exp_store(0);

        // Prefetch V[kb+1] (pair-coalesced; latency hidden by PV mma)
        if (kb + 1 < nkb) {
            const float4* vnxt = vvo + (size_t)(kb+1) * 64 * DHEAD / 4;
            #pragma unroll
            for (int it = 0; it < 8; it++) {
                int idx = tid + it * 128;
                int r  = (idx >> 1) & 63;
                int cg = ((idx >> 6) & 14) | (idx & 1);
                ra[it] = vnxt[r * 16 + cg];
            }
        }

        // O += P @ V, pipelined: exp/store group s+1 overlaps MMA group s
        #pragma unroll
        for (int s = 0; s < 8; s++) {
            if (s < 7) exp_store(s + 1);
            __syncwarp();
            uint32_t a[2][4], bb[4][4];
            #pragma unroll
            for (int mi = 0; mi < 2; mi++)
                LDSM4(a[mi][0], a[mi][1], a[mi][2], a[mi][3], pa_addr[mi] + s*32);
            #pragma unroll
            for (int p = 0; p < 4; p++)
                LDSM4(bb[p][0], bb[p][1], bb[p][2], bb[p][3], vb_addr[p] + s*32);
            #pragma unroll
            for (int mi = 0; mi < 2; mi++)
                #pragma unroll
                for (int p = 0; p < 4; p++) {
                    MMA_TF32(o[mi][2*p],   a[mi], bb[p][0], bb[p][1]);
                    MMA_TF32(o[mi][2*p+1], a[mi], bb[p][2], bb[p][3]);
                }
        }

        // Finalize l (same reduction order as before)
        #pragma unroll
        for (int mi = 0; mi < 2; mi++)
            #pragma unroll
            for (int t = 0; t < 2; t++) {
                float rs = rsv[mi][t];
                rs += __shfl_xor_sync(0xffffffffu, rs, 1);
                rs += __shfl_xor_sync(0xffffffffu, rs, 2);
                l_i[mi][t] = l_i[mi][t] * corr2[mi][t] + rs;
            }
    }

    // Normalize and write tf32-rounded to [B*L, D] (col = h*64 + d)
    const int b = bh >> 4;
    const int h = bh & 15;
    #pragma unroll
    for (int mi = 0; mi < 2; mi++)
        #pragma unroll
        for (int t = 0; t < 2; t++) {
            float inv = 1.0f / l_i[mi][t];
            int row = q0 + wid*32 + mi*16 + g + t*8;
            float* dst = ao + ((size_t)(b * SEQ + row)) * DMODEL + h * DHEAD + tq*2;
            #pragma unroll
            for (int j = 0; j < 8; j++)
                *reinterpret_cast<float2*>(dst + j*8) =
                    make_float2(tf32f(o[mi][j][2*t] * inv),
                                tf32f(o[mi][j][2*t+1] * inv));
        }
}

// ---------------------------------------------------------------------------
extern "C" void kernel_launch(void* const* d_in, const int* in_sizes, int n_in,
                              void* d_out, int out_size)
{
    const float* x  = (const float*)d_in[0];
    const float* Wq = (const float*)d_in[1];
    const float* Wk = (const float*)d_in[2];
    const float* Wv = (const float*)d_in[3];
    const float* Wo = (const float*)d_in[4];
    float* out = (float*)d_out;

    float *qp, *kp, *vp, *aop, *xrp, *wrp;
    cudaGetSymbolAddress((void**)&qp,  g_q);
    cudaGetSymbolAddress((void**)&kp,  g_k);
    cudaGetSymbolAddress((void**)&vp,  g_v);
    cudaGetSymbolAddress((void**)&aop, g_ao);
    cudaGetSymbolAddress((void**)&xrp, g_xr);
    cudaGetSymbolAddress((void**)&wrp, g_wr);

    cudaFuncSetAttribute(gemm_qkv_kernel,
        cudaFuncAttributeMaxDynamicSharedMemorySize, GEMM_SMEM_BYTES);
    cudaFuncSetAttribute(gemm_o_kernel,
        cudaFuncAttributeMaxDynamicSharedMemorySize, GEMM_SMEM_BYTES);
    cudaFuncSetAttribute(attn_tf32,
        cudaFuncAttributeMaxDynamicSharedMemorySize, ATTN_SMEM_BYTES);

    round_all_kernel<<<ROUND_BLOCKS, 256>>>(x, Wq, Wk, Wv, Wo, xrp, wrp);

    dim3 qkv_grid(DMODEL/128, MROWS/128, 3);   // (8, 64, 3)
    gemm_qkv_kernel<<<qkv_grid, 256, GEMM_SMEM_BYTES>>>(xrp, wrp, qp, kp, vp);

    dim3 attn_grid(SEQ/128, BATCH*NHEADS);     // (16, 64)
    attn_tf32<<<attn_grid, 128, ATTN_SMEM_BYTES>>>(qp, kp, vp, aop);

    dim3 o_grid(DMODEL/128, MROWS/128);        // (8, 64)
    gemm_o_kernel<<<o_grid, 256, GEMM_SMEM_BYTES>>>(aop, wrp, out);
}

// round 16
// speedup vs baseline: 2.0229x; 1.8618x over previous
#include <cuda_runtime.h>
#include <cuda_fp16.h>
#include <cstdint>

// Problem constants
#define BATCH 4
#define SEQ   2048
#define DMODEL 1024
#define NHEADS 16
#define DHEAD  64
#define MROWS (BATCH*SEQ)   // 8192

// Scratch (allocation-free: __device__ globals)
__device__ __half g_q [BATCH*NHEADS*SEQ*DHEAD];  // [B,H,L,dh] fp16 (+q scaled)
__device__ __half g_k [BATCH*NHEADS*SEQ*DHEAD];
__device__ __half g_v [BATCH*NHEADS*SEQ*DHEAD];
__device__ __half g_ao[MROWS*DMODEL];            // [B*L, D] fp16
__device__ __half g_xh[MROWS*DMODEL];            // fp16 x
__device__ __half g_wh[4*DMODEL*DMODEL];         // fp16 Wq,Wk,Wv,Wo

struct alignas(8) H4 { __half2 a, b; };

#define LDSM4(r0,r1,r2,r3,addr) \
    asm volatile("ldmatrix.sync.aligned.m8n8.x4.shared.b16 {%0,%1,%2,%3}, [%4];" \
        : "=r"(r0),"=r"(r1),"=r"(r2),"=r"(r3) : "r"(addr))

#define LDSM4T(r0,r1,r2,r3,addr) \
    asm volatile("ldmatrix.sync.aligned.m8n8.x4.trans.shared.b16 {%0,%1,%2,%3}, [%4];" \
        : "=r"(r0),"=r"(r1),"=r"(r2),"=r"(r3) : "r"(addr))

#define MMA_F16(c,a,b0,b1) \
    asm volatile("mma.sync.aligned.m16n8k16.row.col.f32.f16.f16.f32 " \
        "{%0,%1,%2,%3},{%4,%5,%6,%7},{%8,%9},{%0,%1,%2,%3};" \
        : "+f"(c[0]),"+f"(c[1]),"+f"(c[2]),"+f"(c[3]) \
        : "r"(a[0]),"r"(a[1]),"r"(a[2]),"r"(a[3]),"r"(b0),"r"(b1))

#define CP16(dst,src) \
    asm volatile("cp.async.cg.shared.global [%0], [%1], 16;" \
        :: "r"(dst), "l"(src) : "memory")
#define CPCOMMIT() asm volatile("cp.async.commit_group;" ::: "memory")
#define CPWAIT(n)  asm volatile("cp.async.wait_group %0;" :: "n"(n) : "memory")

// ---------------------------------------------------------------------------
// Merged pre-round pass: x (2^21 f4) then Wq,Wk,Wv,Wo (4 x 2^18 f4) -> fp16
// ---------------------------------------------------------------------------
#define N4X  (MROWS*DMODEL/4)          // 2097152 = 2^21
#define N4W  (DMODEL*DMODEL/4)         // 262144  = 2^18
#define ROUND_BLOCKS ((N4X + 4*N4W)/256)

__global__ void __launch_bounds__(256)
round_all_kernel(const float* __restrict__ x,
                 const float* __restrict__ Wq, const float* __restrict__ Wk,
                 const float* __restrict__ Wv, const float* __restrict__ Wo,
                 __half* __restrict__ xh, __half* __restrict__ wh)
{
    int i = blockIdx.x * 256 + threadIdx.x;
    const float* src;
    __half* dst;
    if (i < N4X) {
        src = x; dst = xh;
    } else {
        int j = i - N4X;
        int z = j >> 18;
        i = j & (N4W - 1);
        src = (z == 0) ? Wq : (z == 1) ? Wk : (z == 2) ? Wv : Wo;
        dst = wh + (size_t)z * DMODEL * DMODEL;
    }
    float4 v = reinterpret_cast<const float4*>(src)[i];
    H4 h;
    h.a = __floats2half2_rn(v.x, v.y);
    h.b = __floats2half2_rn(v.z, v.w);
    *reinterpret_cast<H4*>(dst + (size_t)i * 4) = h;
}

// ---------------------------------------------------------------------------
// fp16 GEMM: C = A @ W^T (fp32 accum). cp.async 3-stage pipeline, BK=64.
// CTA 128x128x64, 256 threads (8 warps 2x4), warp tile 64x32.
// Stage = A[128x72] + W[128x72] fp16 = 36864 B; 3 stages = 110592 B (2 CTA/SM).
// ---------------------------------------------------------------------------
#define GROWB 144                     // row stride bytes (72 fp16)
#define GWOFFB 18432                  // W offset in stage (bytes)
#define GSTB  36864                   // stage bytes
#define GEMM_SMEM_BYTES (3*GSTB)      // 110592

__device__ __forceinline__ void gemm_load_stage(
    const __half* __restrict__ A, const __half* __restrict__ W,
    int m0, int n0, int k0, uint32_t sb, int tid)
{
    #pragma unroll
    for (int it = 0; it < 4; it++) {
        int idx = tid + it * 256;
        int row = idx >> 3, cg = idx & 7;       // cg = 16B chunk (8 fp16)
        CP16(sb + (uint32_t)(row*GROWB + cg*16),
             (const void*)(A + (size_t)(m0 + row) * DMODEL + k0 + cg*8));
        CP16(sb + (uint32_t)(GWOFFB + row*GROWB + cg*16),
             (const void*)(W + (size_t)(n0 + row) * DMODEL + k0 + cg*8));
    }
}

template<int HALFOUT>
__device__ __forceinline__ void gemm_core(
    const __half* __restrict__ A, const __half* __restrict__ W,
    void* __restrict__ Cv, float scale)
{
    extern __shared__ float sm[];
    const int tid  = threadIdx.x;
    const int lane = tid & 31;
    const int wid  = tid >> 5;
    const int m0 = blockIdx.y * 128;
    const int n0 = blockIdx.x * 128;
    const int wm = (wid & 1) * 64;
    const int wn = (wid >> 1) * 32;

    float c[4][4][4];
    #pragma unroll
    for (int i = 0; i < 4; i++)
        #pragma unroll
        for (int j = 0; j < 4; j++)
            #pragma unroll
            for (int r = 0; r < 4; r++) c[i][j][r] = 0.0f;

    uint32_t sb = (uint32_t)__cvta_generic_to_shared(sm);
    uint32_t a_addr[4], b_addr[2];
    #pragma unroll
    for (int i = 0; i < 4; i++)
        a_addr[i] = sb + (uint32_t)((wm + i*16 + (lane & 15)) * GROWB
                                    + (lane >> 4) * 16);
    #pragma unroll
    for (int p = 0; p < 2; p++)
        b_addr[p] = sb + (uint32_t)(GWOFFB
            + (wn + p*16 + ((lane >> 4) & 1) * 8 + (lane & 7)) * GROWB
            + ((lane >> 3) & 1) * 16);

    const int NK = DMODEL / 64;   // 16 k-slabs

    gemm_load_stage(A, W, m0, n0, 0,   sb,          tid); CPCOMMIT();
    gemm_load_stage(A, W, m0, n0, 64,  sb + GSTB,   tid); CPCOMMIT();
    gemm_load_stage(A, W, m0, n0, 128, sb + 2*GSTB, tid); CPCOMMIT();

    #pragma unroll 1
    for (int i = 0; i < NK; i++) {
        CPWAIT(2);
        __syncthreads();

        const uint32_t soff = (uint32_t)(i % 3) * GSTB;
        #pragma unroll
        for (int s = 0; s < 4; s++) {          // k16 steps
            uint32_t a[4][4], bb[2][4];
            #pragma unroll
            for (int ii = 0; ii < 4; ii++)
                LDSM4(a[ii][0], a[ii][1], a[ii][2], a[ii][3],
                      a_addr[ii] + soff + s*32);
            #pragma unroll
            for (int p = 0; p < 2; p++)
                LDSM4(bb[p][0], bb[p][1], bb[p][2], bb[p][3],
                      b_addr[p] + soff + s*32);
            #pragma unroll
            for (int ii = 0; ii < 4; ii++)
                #pragma unroll
                for (int p = 0; p < 2; p++) {
                    MMA_F16(c[ii][2*p],   a[ii], bb[p][0], bb[p][1]);
                    MMA_F16(c[ii][2*p+1], a[ii], bb[p][2], bb[p][3]);
                }
        }
        __syncthreads();
        if (i + 3 < NK)
            gemm_load_stage(A, W, m0, n0, (i+3)*64, sb + soff, tid);
        CPCOMMIT();
    }

    // Epilogue
    const int g  = lane >> 2;
    const int tq = lane & 3;
    #pragma unroll
    for (int i = 0; i < 4; i++) {
        #pragma unroll
        for (int j = 0; j < 4; j++) {
            int col = n0 + wn + j*8 + tq*2;
            #pragma unroll
            for (int t = 0; t < 2; t++) {
                int row = m0 + wm + i*16 + g + t*8;
                float v0 = c[i][j][2*t] * scale, v1 = c[i][j][2*t+1] * scale;
                if (HALFOUT) {
                    // permuted write into [B,H,L,dh] fp16
                    int b = row >> 11, l = row & (SEQ - 1);
                    int h = col >> 6, d = col & 63;
                    __half* C = (__half*)Cv;
                    *reinterpret_cast<__half2*>(
                        &C[(((size_t)(b*NHEADS + h)) * SEQ + l) * DHEAD + d]) =
                        __floats2half2_rn(v0, v1);
                } else {
                    float* C = (float*)Cv;
                    *reinterpret_cast<float2*>(&C[(size_t)row * DMODEL + col]) =
                        make_float2(v0, v1);
                }
            }
        }
    }
}

__global__ void __launch_bounds__(256, 2)
gemm_qkv_kernel(const __half* __restrict__ xh, const __half* __restrict__ wh,
                __half* __restrict__ q, __half* __restrict__ k,
                __half* __restrict__ v)
{
    const int z = blockIdx.z;
    const __half* W = wh + (size_t)z * DMODEL * DMODEL;
    __half* C = (z == 0) ? q : (z == 1) ? k : v;
    float scale = (z == 0) ? 0.125f : 1.0f;
    gemm_core<1>(xh, W, (void*)C, scale);
}

__global__ void __launch_bounds__(256, 2)
gemm_o_kernel(const __half* __restrict__ aoh, const __half* __restrict__ wh,
              float* __restrict__ out)
{
    gemm_core<0>(aoh, wh + (size_t)3 * DMODEL * DMODEL, (void*)out, 1.0f);
}

// ---------------------------------------------------------------------------
// Flash attention, fp16 mma (fp32 accum). CTA = 128 q x (b,h), 128 threads,
// 4 warps, warp tile m32 x n64, BK=64. K and V double-buffered via cp.async
// (V stored row-major, read with ldmatrix.trans — no transpose pass).
// smem bytes: Qs[128x144] | Ps[128x144] | Ks[2][64x144] | Vs[2][64x144]
//           = 18432 + 18432 + 18432 + 18432 = 73728 B  -> 2 CTAs/SM easily.
// ---------------------------------------------------------------------------
#define AQSB 0
#define APSB 18432
#define AKSB 36864
#define AVSB 55296
#define AKVSTG 9216                   // one K or V stage (64*144)
#define ATTN_SMEM_BYTES 73728

__global__ void __launch_bounds__(128, 2)
attn_f16(const __half* __restrict__ gq, const __half* __restrict__ gk,
         const __half* __restrict__ gv, __half* __restrict__ ao)
{
    extern __shared__ float sm[];

    const int tid  = threadIdx.x;
    const int lane = tid & 31;
    const int wid  = tid >> 5;                    // 0..3, owns 32 q rows
    const int bh = blockIdx.y;
    const int q0 = ((int)gridDim.x - 1 - (int)blockIdx.x) * 128;  // heavy first

    uint32_t smb  = (uint32_t)__cvta_generic_to_shared(sm);
    uint32_t qs_b = smb + AQSB;
    uint32_t ps_b = smb + APSB;
    uint32_t ks_b = smb + AKSB;
    uint32_t vs_b = smb + AVSB;
    __half* Ps = reinterpret_cast<__half*>(reinterpret_cast<char*>(sm) + APSB);

    const __half* qbase = gq + ((size_t)bh * SEQ + q0) * DHEAD;
    const __half* kko = gk + (size_t)bh * SEQ * DHEAD;
    const __half* vvo = gv + (size_t)bh * SEQ * DHEAD;

    // Prologue: cp.async Q (128 rows) + K0 + V0 (64 rows each), one group
    #pragma unroll
    for (int it = 0; it < 8; it++) {
        int idx = tid + it * 128;                 // 1024 = 128 rows x 8 cg
        int row = idx >> 3, cg = idx & 7;
        CP16(qs_b + (uint32_t)(row*144 + cg*16),
             (const void*)(qbase + (size_t)row * DHEAD + cg*8));
    }
    #pragma unroll
    for (int it = 0; it < 4; it++) {
        int idx = tid + it * 128;                 // 512 = 64 rows x 8 cg
        int row = idx >> 3, cg = idx & 7;
        CP16(ks_b + (uint32_t)(row*144 + cg*16),
             (const void*)(kko + (size_t)row * DHEAD + cg*8));
        CP16(vs_b + (uint32_t)(row*144 + cg*16),
             (const void*)(vvo + (size_t)row * DHEAD + cg*8));
    }
    CPCOMMIT();

    // LDSM addresses
    uint32_t qa_addr[2], pa_addr[2];
    #pragma unroll
    for (int mi = 0; mi < 2; mi++) {
        uint32_t roff = (uint32_t)((wid*32 + mi*16 + (lane & 15)) * 144
                                   + (lane >> 4) * 16);
        qa_addr[mi] = qs_b + roff;
        pa_addr[mi] = ps_b + roff;
    }
    uint32_t kb_off[4], vb_off[4];
    #pragma unroll
    for (int vp = 0; vp < 4; vp++) {
        // K (non-trans): rows = keys, x4 covers n16 x k16
        kb_off[vp] = (uint32_t)((vp*16 + ((lane >> 4) & 1) * 8 + (lane & 7)) * 144
                                + ((lane >> 3) & 1) * 16);
        // V (.trans): rows = keys (within k16 step), cols = d-chunks
        vb_off[vp] = (uint32_t)((((lane >> 3) & 1) * 8 + (lane & 7)) * 144
                                + (vp*2 + (lane >> 4)) * 16);
    }

    float m_i[2][2] = {{-1e30f, -1e30f}, {-1e30f, -1e30f}};
    float l_i[2][2] = {{0.0f, 0.0f}, {0.0f, 0.0f}};
    float o[2][8][4];
    #pragma unroll
    for (int mi = 0; mi < 2; mi++)
        #pragma unroll
        for (int j = 0; j < 8; j++)
            #pragma unroll
            for (int r = 0; r < 4; r++) o[mi][j][r] = 0.0f;

    const int g  = lane >> 2;
    const int tq = lane & 3;
    int pbase[2][2];   // byte offset within Ps (in halves: row*72 + tq*2)
    #pragma unroll
    for (int mi = 0; mi < 2; mi++)
        #pragma unroll
        for (int t = 0; t < 2; t++)
            pbase[mi][t] = (wid*32 + mi*16 + g + t*8) * 72 + tq*2;

    const int nkb = (q0 + 128) / 64;
    #pragma unroll 1
    for (int kb = 0; kb < nkb; kb++) {
        const int cur = kb & 1;
        const uint32_t kcur = ks_b + (uint32_t)cur * AKVSTG;
        const uint32_t vcur = vs_b + (uint32_t)cur * AKVSTG;

        CPWAIT(0);           // group kb (and Q on kb=0) complete
        __syncthreads();     // all warps past iter kb-1 reads of buf cur^1

        // Issue K/V[kb+1] into the other stage — overlaps whole iteration
        if (kb + 1 < nkb) {
            const __half* knxt = kko + (size_t)(kb+1) * 64 * DHEAD;
            const __half* vnxt = vvo + (size_t)(kb+1) * 64 * DHEAD;
            uint32_t kdst = ks_b + (uint32_t)(cur ^ 1) * AKVSTG;
            uint32_t vdst = vs_b + (uint32_t)(cur ^ 1) * AKVSTG;
            #pragma unroll
            for (int it = 0; it < 4; it++) {
                int idx = tid + it * 128;
                int row = idx >> 3, cg = idx & 7;
                CP16(kdst + (uint32_t)(row*144 + cg*16),
                     (const void*)(knxt + (size_t)row * DHEAD + cg*8));
                CP16(vdst + (uint32_t)(row*144 + cg*16),
                     (const void*)(vnxt + (size_t)row * DHEAD + cg*8));
            }
        }
        CPCOMMIT();

        // S = Q @ K^T : warp m32 x n64, 4 k16-steps
        float sf[2][8][4];
        #pragma unroll
        for (int mi = 0; mi < 2; mi++)
            #pragma unroll
            for (int j = 0; j < 8; j++)
                #pragma unroll
                for (int r = 0; r < 4; r++) sf[mi][j][r] = 0.0f;

        #pragma unroll
        for (int s = 0; s < 4; s++) {
            uint32_t a[2][4], bb[4][4];
            #pragma unroll
            for (int mi = 0; mi < 2; mi++)
                LDSM4(a[mi][0], a[mi][1], a[mi][2], a[mi][3],
                      qa_addr[mi] + s*32);
            #pragma unroll
            for (int vp = 0; vp < 4; vp++)
                LDSM4(bb[vp][0], bb[vp][1], bb[vp][2], bb[vp][3],
                      kcur + kb_off[vp] + s*32);
            #pragma unroll
            for (int mi = 0; mi < 2; mi++)
                #pragma unroll
                for (int vp = 0; vp < 4; vp++) {
                    MMA_F16(sf[mi][2*vp],   a[mi], bb[vp][0], bb[vp][1]);
                    MMA_F16(sf[mi][2*vp+1], a[mi], bb[vp][2], bb[vp][3]);
                }
        }

        // Causal mask (near diagonal only)
        const int k0 = kb * 64;
        if (k0 + 63 > q0 + wid*32) {
            #pragma unroll
            for (int mi = 0; mi < 2; mi++)
                #pragma unroll
                for (int t = 0; t < 2; t++) {
                    int qg = q0 + wid*32 + mi*16 + g + t*8;
                    #pragma unroll
                    for (int j = 0; j < 8; j++) {
                        int kg = k0 + j*8 + tq*2;
                        if (kg   > qg) sf[mi][j][2*t]   = -1e30f;
                        if (kg+1 > qg) sf[mi][j][2*t+1] = -1e30f;
                    }
                }
        }

        // Softmax phase 1: row max, corr, o-scale
        float corr2[2][2], rsv[2][2];
        #pragma unroll
        for (int mi = 0; mi < 2; mi++)
            #pragma unroll
            for (int t = 0; t < 2; t++) {
                float mx = -1e30f;
                #pragma unroll
                for (int j = 0; j < 8; j++)
                    mx = fmaxf(mx, fmaxf(sf[mi][j][2*t], sf[mi][j][2*t+1]));
                mx = fmaxf(mx, __shfl_xor_sync(0xffffffffu, mx, 1));
                mx = fmaxf(mx, __shfl_xor_sync(0xffffffffu, mx, 2));
                float newm = fmaxf(m_i[mi][t], mx);
                corr2[mi][t] = __expf(m_i[mi][t] - newm);
                m_i[mi][t] = newm;
                rsv[mi][t] = 0.0f;
                #pragma unroll
                for (int j = 0; j < 8; j++) {
                    o[mi][j][2*t]   *= corr2[mi][t];
                    o[mi][j][2*t+1] *= corr2[mi][t];
                }
            }

        // exp + fp16 store of P group jj
        auto exp_store = [&](int jj) {
            #pragma unroll
            for (int mi = 0; mi < 2; mi++)
                #pragma unroll
                for (int t = 0; t < 2; t++) {
                    float p0 = __expf(sf[mi][jj][2*t]   - m_i[mi][t]);
                    float p1 = __expf(sf[mi][jj][2*t+1] - m_i[mi][t]);
                    rsv[mi][t] += p0 + p1;
                    *reinterpret_cast<__half2*>(&Ps[pbase[mi][t] + jj*8]) =
                        __floats2half2_rn(p0, p1);
                }
        };
        exp_store(0);
        exp_store(1);

        // O += P @ V, pipelined: exp/store groups 2s+2,2s+3 overlap MMA step s
        #pragma unroll
        for (int s = 0; s < 4; s++) {
            if (s < 3) { exp_store(2*s + 2); exp_store(2*s + 3); }
            __syncwarp();
            uint32_t a[2][4], bb[4][4];
            #pragma unroll
            for (int mi = 0; mi < 2; mi++)
                LDSM4(a[mi][0], a[mi][1], a[mi][2], a[mi][3],
                      pa_addr[mi] + s*32);
            #pragma unroll
            for (int vp = 0; vp < 4; vp++)
                LDSM4T(bb[vp][0], bb[vp][1], bb[vp][2], bb[vp][3],
                       vcur + vb_off[vp] + (uint32_t)s * (16*144));
            #pragma unroll
            for (int mi = 0; mi < 2; mi++)
                #pragma unroll
                for (int vp = 0; vp < 4; vp++) {
                    MMA_F16(o[mi][2*vp],   a[mi], bb[vp][0], bb[vp][1]);
                    MMA_F16(o[mi][2*vp+1], a[mi], bb[vp][2], bb[vp][3]);
                }
        }

        // Finalize l
        #pragma unroll
        for (int mi = 0; mi < 2; mi++)
            #pragma unroll
            for (int t = 0; t < 2; t++) {
                float rs = rsv[mi][t];
                rs += __shfl_xor_sync(0xffffffffu, rs, 1);
                rs += __shfl_xor_sync(0xffffffffu, rs, 2);
                l_i[mi][t] = l_i[mi][t] * corr2[mi][t] + rs;
            }
    }

    // Normalize and write fp16 to [B*L, D] (col = h*64 + d)
    const int b = bh >> 4;
    const int h = bh & 15;
    #pragma unroll
    for (int mi = 0; mi < 2; mi++)
        #pragma unroll
        for (int t = 0; t < 2; t++) {
            float inv = 1.0f / l_i[mi][t];
            int row = q0 + wid*32 + mi*16 + g + t*8;
            __half* dst = ao + ((size_t)(b * SEQ + row)) * DMODEL
                        + h * DHEAD + tq*2;
            #pragma unroll
            for (int j = 0; j < 8; j++)
                *reinterpret_cast<__half2*>(dst + j*8) =
                    __floats2half2_rn(o[mi][j][2*t] * inv,
                                      o[mi][j][2*t+1] * inv);
        }
}

// ---------------------------------------------------------------------------
extern "C" void kernel_launch(void* const* d_in, const int* in_sizes, int n_in,
                              void* d_out, int out_size)
{
    const float* x  = (const float*)d_in[0];
    const float* Wq = (const float*)d_in[1];
    const float* Wk = (const float*)d_in[2];
    const float* Wv = (const float*)d_in[3];
    const float* Wo = (const float*)d_in[4];
    float* out = (float*)d_out;

    __half *qp, *kp, *vp, *aop, *xhp, *whp;
    cudaGetSymbolAddress((void**)&qp,  g_q);
    cudaGetSymbolAddress((void**)&kp,  g_k);
    cudaGetSymbolAddress((void**)&vp,  g_v);
    cudaGetSymbolAddress((void**)&aop, g_ao);
    cudaGetSymbolAddress((void**)&xhp, g_xh);
    cudaGetSymbolAddress((void**)&whp, g_wh);

    cudaFuncSetAttribute(gemm_qkv_kernel,
        cudaFuncAttributeMaxDynamicSharedMemorySize, GEMM_SMEM_BYTES);
    cudaFuncSetAttribute(gemm_o_kernel,
        cudaFuncAttributeMaxDynamicSharedMemorySize, GEMM_SMEM_BYTES);
    cudaFuncSetAttribute(attn_f16,
        cudaFuncAttributeMaxDynamicSharedMemorySize, ATTN_SMEM_BYTES);

    round_all_kernel<<<ROUND_BLOCKS, 256>>>(x, Wq, Wk, Wv, Wo, xhp, whp);

    dim3 qkv_grid(DMODEL/128, MROWS/128, 3);   // (8, 64, 3)
    gemm_qkv_kernel<<<qkv_grid, 256, GEMM_SMEM_BYTES>>>(xhp, whp, qp, kp, vp);

    dim3 attn_grid(SEQ/128, BATCH*NHEADS);     // (16, 64)
    attn_f16<<<attn_grid, 128, ATTN_SMEM_BYTES>>>(qp, kp, vp, aop);

    dim3 o_grid(DMODEL/128, MROWS/128);        // (8, 64)
    gemm_o_kernel<<<o_grid, 256, GEMM_SMEM_BYTES>>>(aop, whp, out);
}

// round 17
// speedup vs baseline: 2.0245x; 1.0008x over previous
#include <cuda_runtime.h>
#include <cuda_fp16.h>
#include <cstdint>

// Problem constants
#define BATCH 4
#define SEQ   2048
#define DMODEL 1024
#define NHEADS 16
#define DHEAD  64
#define MROWS (BATCH*SEQ)   // 8192

// Scratch (allocation-free: __device__ globals)
__device__ __half g_q [BATCH*NHEADS*SEQ*DHEAD];  // [B,H,L,dh] fp16 (+q scaled)
__device__ __half g_k [BATCH*NHEADS*SEQ*DHEAD];
__device__ __half g_v [BATCH*NHEADS*SEQ*DHEAD];
__device__ __half g_ao[MROWS*DMODEL];            // [B*L, D] fp16
__device__ __half g_xh[MROWS*DMODEL];            // fp16 x
__device__ __half g_wh[4*DMODEL*DMODEL];         // fp16 Wq,Wk,Wv,Wo

struct alignas(8) H4 { __half2 a, b; };

#define LDSM4(r0,r1,r2,r3,addr) \
    asm volatile("ldmatrix.sync.aligned.m8n8.x4.shared.b16 {%0,%1,%2,%3}, [%4];" \
        : "=r"(r0),"=r"(r1),"=r"(r2),"=r"(r3) : "r"(addr))

#define LDSM4T(r0,r1,r2,r3,addr) \
    asm volatile("ldmatrix.sync.aligned.m8n8.x4.trans.shared.b16 {%0,%1,%2,%3}, [%4];" \
        : "=r"(r0),"=r"(r1),"=r"(r2),"=r"(r3) : "r"(addr))

#define MMA_F16(c,a,b0,b1) \
    asm volatile("mma.sync.aligned.m16n8k16.row.col.f32.f16.f16.f32 " \
        "{%0,%1,%2,%3},{%4,%5,%6,%7},{%8,%9},{%0,%1,%2,%3};" \
        : "+f"(c[0]),"+f"(c[1]),"+f"(c[2]),"+f"(c[3]) \
        : "r"(a[0]),"r"(a[1]),"r"(a[2]),"r"(a[3]),"r"(b0),"r"(b1))

#define CP16(dst,src) \
    asm volatile("cp.async.cg.shared.global [%0], [%1], 16;" \
        :: "r"(dst), "l"(src) : "memory")
#define CPCOMMIT() asm volatile("cp.async.commit_group;" ::: "memory")
#define CPWAIT(n)  asm volatile("cp.async.wait_group %0;" :: "n"(n) : "memory")

// ---------------------------------------------------------------------------
// Merged pre-round pass: x (2^21 f4) then Wq,Wk,Wv,Wo (4 x 2^18 f4) -> fp16
// ---------------------------------------------------------------------------
#define N4X  (MROWS*DMODEL/4)          // 2097152 = 2^21
#define N4W  (DMODEL*DMODEL/4)         // 262144  = 2^18
#define ROUND_BLOCKS ((N4X + 4*N4W)/256)

__global__ void __launch_bounds__(256)
round_all_kernel(const float* __restrict__ x,
                 const float* __restrict__ Wq, const float* __restrict__ Wk,
                 const float* __restrict__ Wv, const float* __restrict__ Wo,
                 __half* __restrict__ xh, __half* __restrict__ wh)
{
    int i = blockIdx.x * 256 + threadIdx.x;
    const float* src;
    __half* dst;
    if (i < N4X) {
        src = x; dst = xh;
    } else {
        int j = i - N4X;
        int z = j >> 18;
        i = j & (N4W - 1);
        src = (z == 0) ? Wq : (z == 1) ? Wk : (z == 2) ? Wv : Wo;
        dst = wh + (size_t)z * DMODEL * DMODEL;
    }
    float4 v = reinterpret_cast<const float4*>(src)[i];
    H4 h;
    h.a = __floats2half2_rn(v.x, v.y);
    h.b = __floats2half2_rn(v.z, v.w);
    *reinterpret_cast<H4*>(dst + (size_t)i * 4) = h;
}

// ---------------------------------------------------------------------------
// fp16 GEMM: C = A @ W^T (fp32 accum). 3-stage cp.async pipeline, BK=64,
// SINGLE barrier per iteration (load-first, distance-2 lookahead):
//   CPWAIT(1); sync; load(i+2) -> slot (i+2)%3; commit; MMA(i).
// CTA 128x128x64, 256 threads (8 warps 2x4), warp tile 64x32, 2 CTAs/SM.
// ---------------------------------------------------------------------------
#define GROWB 144                     // row stride bytes (72 fp16)
#define GWOFFB 18432                  // W offset in stage (bytes)
#define GSTB  36864                   // stage bytes
#define GEMM_SMEM_BYTES (3*GSTB)      // 110592

__device__ __forceinline__ void gemm_load_stage(
    const __half* __restrict__ A, const __half* __restrict__ W,
    int m0, int n0, int k0, uint32_t sb, int tid)
{
    #pragma unroll
    for (int it = 0; it < 4; it++) {
        int idx = tid + it * 256;
        int row = idx >> 3, cg = idx & 7;       // cg = 16B chunk (8 fp16)
        CP16(sb + (uint32_t)(row*GROWB + cg*16),
             (const void*)(A + (size_t)(m0 + row) * DMODEL + k0 + cg*8));
        CP16(sb + (uint32_t)(GWOFFB + row*GROWB + cg*16),
             (const void*)(W + (size_t)(n0 + row) * DMODEL + k0 + cg*8));
    }
}

template<int HALFOUT>
__device__ __forceinline__ void gemm_core(
    const __half* __restrict__ A, const __half* __restrict__ W,
    void* __restrict__ Cv, float scale)
{
    extern __shared__ float sm[];
    const int tid  = threadIdx.x;
    const int lane = tid & 31;
    const int wid  = tid >> 5;
    const int m0 = blockIdx.y * 128;
    const int n0 = blockIdx.x * 128;
    const int wm = (wid & 1) * 64;
    const int wn = (wid >> 1) * 32;

    float c[4][4][4];
    #pragma unroll
    for (int i = 0; i < 4; i++)
        #pragma unroll
        for (int j = 0; j < 4; j++)
            #pragma unroll
            for (int r = 0; r < 4; r++) c[i][j][r] = 0.0f;

    uint32_t sb = (uint32_t)__cvta_generic_to_shared(sm);
    uint32_t a_addr[4], b_addr[2];
    #pragma unroll
    for (int i = 0; i < 4; i++)
        a_addr[i] = sb + (uint32_t)((wm + i*16 + (lane & 15)) * GROWB
                                    + (lane >> 4) * 16);
    #pragma unroll
    for (int p = 0; p < 2; p++)
        b_addr[p] = sb + (uint32_t)(GWOFFB
            + (wn + p*16 + ((lane >> 4) & 1) * 8 + (lane & 7)) * GROWB
            + ((lane >> 3) & 1) * 16);

    const int NK = DMODEL / 64;   // 16 k-slabs

    gemm_load_stage(A, W, m0, n0, 0,  sb,        tid); CPCOMMIT();
    gemm_load_stage(A, W, m0, n0, 64, sb + GSTB, tid); CPCOMMIT();

    #pragma unroll 1
    for (int i = 0; i < NK; i++) {
        CPWAIT(1);          // stage i landed (≤1 group outstanding)
        __syncthreads();    // visibility + all warps done reading slot (i+2)%3
        if (i + 2 < NK)
            gemm_load_stage(A, W, m0, n0, (i+2)*64,
                            sb + (uint32_t)((i+2) % 3) * GSTB, tid);
        CPCOMMIT();         // uniform group accounting

        const uint32_t soff = (uint32_t)(i % 3) * GSTB;
        #pragma unroll
        for (int s = 0; s < 4; s++) {          // k16 steps
            uint32_t a[4][4], bb[2][4];
            #pragma unroll
            for (int ii = 0; ii < 4; ii++)
                LDSM4(a[ii][0], a[ii][1], a[ii][2], a[ii][3],
                      a_addr[ii] + soff + s*32);
            #pragma unroll
            for (int p = 0; p < 2; p++)
                LDSM4(bb[p][0], bb[p][1], bb[p][2], bb[p][3],
                      b_addr[p] + soff + s*32);
            #pragma unroll
            for (int ii = 0; ii < 4; ii++)
                #pragma unroll
                for (int p = 0; p < 2; p++) {
                    MMA_F16(c[ii][2*p],   a[ii], bb[p][0], bb[p][1]);
                    MMA_F16(c[ii][2*p+1], a[ii], bb[p][2], bb[p][3]);
                }
        }
    }

    // Epilogue
    const int g  = lane >> 2;
    const int tq = lane & 3;
    #pragma unroll
    for (int i = 0; i < 4; i++) {
        #pragma unroll
        for (int j = 0; j < 4; j++) {
            int col = n0 + wn + j*8 + tq*2;
            #pragma unroll
            for (int t = 0; t < 2; t++) {
                int row = m0 + wm + i*16 + g + t*8;
                float v0 = c[i][j][2*t] * scale, v1 = c[i][j][2*t+1] * scale;
                if (HALFOUT) {
                    int b = row >> 11, l = row & (SEQ - 1);
                    int h = col >> 6, d = col & 63;
                    __half* C = (__half*)Cv;
                    *reinterpret_cast<__half2*>(
                        &C[(((size_t)(b*NHEADS + h)) * SEQ + l) * DHEAD + d]) =
                        __floats2half2_rn(v0, v1);
                } else {
                    float* C = (float*)Cv;
                    *reinterpret_cast<float2*>(&C[(size_t)row * DMODEL + col]) =
                        make_float2(v0, v1);
                }
            }
        }
    }
}

__global__ void __launch_bounds__(256, 2)
gemm_qkv_kernel(const __half* __restrict__ xh, const __half* __restrict__ wh,
                __half* __restrict__ q, __half* __restrict__ k,
                __half* __restrict__ v)
{
    const int z = blockIdx.z;
    const __half* W = wh + (size_t)z * DMODEL * DMODEL;
    __half* C = (z == 0) ? q : (z == 1) ? k : v;
    float scale = (z == 0) ? 0.125f : 1.0f;
    gemm_core<1>(xh, W, (void*)C, scale);
}

__global__ void __launch_bounds__(256, 2)
gemm_o_kernel(const __half* __restrict__ aoh, const __half* __restrict__ wh,
              float* __restrict__ out)
{
    gemm_core<0>(aoh, wh + (size_t)3 * DMODEL * DMODEL, (void*)out, 1.0f);
}

// ---------------------------------------------------------------------------
// Flash attention, fp16 mma (round 16 — current best, unchanged).
// CTA = 128 q x (b,h), 128 threads, 4 warps, warp tile m32 x n64, BK=64.
// K and V double-buffered via cp.async (V read with ldmatrix.trans).
// smem: Qs[128x144] | Ps[128x144] | Ks[2][64x144] | Vs[2][64x144] = 73728 B
// ---------------------------------------------------------------------------
#define AQSB 0
#define APSB 18432
#define AKSB 36864
#define AVSB 55296
#define AKVSTG 9216                   // one K or V stage (64*144)
#define ATTN_SMEM_BYTES 73728

__global__ void __launch_bounds__(128, 2)
attn_f16(const __half* __restrict__ gq, const __half* __restrict__ gk,
         const __half* __restrict__ gv, __half* __restrict__ ao)
{
    extern __shared__ float sm[];

    const int tid  = threadIdx.x;
    const int lane = tid & 31;
    const int wid  = tid >> 5;                    // 0..3, owns 32 q rows
    const int bh = blockIdx.y;
    const int q0 = ((int)gridDim.x - 1 - (int)blockIdx.x) * 128;  // heavy first

    uint32_t smb  = (uint32_t)__cvta_generic_to_shared(sm);
    uint32_t qs_b = smb + AQSB;
    uint32_t ps_b = smb + APSB;
    uint32_t ks_b = smb + AKSB;
    uint32_t vs_b = smb + AVSB;
    __half* Ps = reinterpret_cast<__half*>(reinterpret_cast<char*>(sm) + APSB);

    const __half* qbase = gq + ((size_t)bh * SEQ + q0) * DHEAD;
    const __half* kko = gk + (size_t)bh * SEQ * DHEAD;
    const __half* vvo = gv + (size_t)bh * SEQ * DHEAD;

    // Prologue: cp.async Q (128 rows) + K0 + V0 (64 rows each), one group
    #pragma unroll
    for (int it = 0; it < 8; it++) {
        int idx = tid + it * 128;                 // 1024 = 128 rows x 8 cg
        int row = idx >> 3, cg = idx & 7;
        CP16(qs_b + (uint32_t)(row*144 + cg*16),
             (const void*)(qbase + (size_t)row * DHEAD + cg*8));
    }
    #pragma unroll
    for (int it = 0; it < 4; it++) {
        int idx = tid + it * 128;                 // 512 = 64 rows x 8 cg
        int row = idx >> 3, cg = idx & 7;
        CP16(ks_b + (uint32_t)(row*144 + cg*16),
             (const void*)(kko + (size_t)row * DHEAD + cg*8));
        CP16(vs_b + (uint32_t)(row*144 + cg*16),
             (const void*)(vvo + (size_t)row * DHEAD + cg*8));
    }
    CPCOMMIT();

    // LDSM addresses
    uint32_t qa_addr[2], pa_addr[2];
    #pragma unroll
    for (int mi = 0; mi < 2; mi++) {
        uint32_t roff = (uint32_t)((wid*32 + mi*16 + (lane & 15)) * 144
                                   + (lane >> 4) * 16);
        qa_addr[mi] = qs_b + roff;
        pa_addr[mi] = ps_b + roff;
    }
    uint32_t kb_off[4], vb_off[4];
    #pragma unroll
    for (int vp = 0; vp < 4; vp++) {
        kb_off[vp] = (uint32_t)((vp*16 + ((lane >> 4) & 1) * 8 + (lane & 7)) * 144
                                + ((lane >> 3) & 1) * 16);
        vb_off[vp] = (uint32_t)((((lane >> 3) & 1) * 8 + (lane & 7)) * 144
                                + (vp*2 + (lane >> 4)) * 16);
    }

    float m_i[2][2] = {{-1e30f, -1e30f}, {-1e30f, -1e30f}};
    float l_i[2][2] = {{0.0f, 0.0f}, {0.0f, 0.0f}};
    float o[2][8][4];
    #pragma unroll
    for (int mi = 0; mi < 2; mi++)
        #pragma unroll
        for (int j = 0; j < 8; j++)
            #pragma unroll
            for (int r = 0; r < 4; r++) o[mi][j][r] = 0.0f;

    const int g  = lane >> 2;
    const int tq = lane & 3;
    int pbase[2][2];
    #pragma unroll
    for (int mi = 0; mi < 2; mi++)
        #pragma unroll
        for (int t = 0; t < 2; t++)
            pbase[mi][t] = (wid*32 + mi*16 + g + t*8) * 72 + tq*2;

    const int nkb = (q0 + 128) / 64;
    #pragma unroll 1
    for (int kb = 0; kb < nkb; kb++) {
        const int cur = kb & 1;
        const uint32_t kcur = ks_b + (uint32_t)cur * AKVSTG;
        const uint32_t vcur = vs_b + (uint32_t)cur * AKVSTG;

        CPWAIT(0);           // group kb (and Q on kb=0) complete
        __syncthreads();     // all warps past iter kb-1 reads of buf cur^1

        // Issue K/V[kb+1] into the other stage — overlaps whole iteration
        if (kb + 1 < nkb) {
            const __half* knxt = kko + (size_t)(kb+1) * 64 * DHEAD;
            const __half* vnxt = vvo + (size_t)(kb+1) * 64 * DHEAD;
            uint32_t kdst = ks_b + (uint32_t)(cur ^ 1) * AKVSTG;
            uint32_t vdst = vs_b + (uint32_t)(cur ^ 1) * AKVSTG;
            #pragma unroll
            for (int it = 0; it < 4; it++) {
                int idx = tid + it * 128;
                int row = idx >> 3, cg = idx & 7;
                CP16(kdst + (uint32_t)(row*144 + cg*16),
                     (const void*)(knxt + (size_t)row * DHEAD + cg*8));
                CP16(vdst + (uint32_t)(row*144 + cg*16),
                     (const void*)(vnxt + (size_t)row * DHEAD + cg*8));
            }
        }
        CPCOMMIT();

        // S = Q @ K^T : warp m32 x n64, 4 k16-steps
        float sf[2][8][4];
        #pragma unroll
        for (int mi = 0; mi < 2; mi++)
            #pragma unroll
            for (int j = 0; j < 8; j++)
                #pragma unroll
                for (int r = 0; r < 4; r++) sf[mi][j][r] = 0.0f;

        #pragma unroll
        for (int s = 0; s < 4; s++) {
            uint32_t a[2][4], bb[4][4];
            #pragma unroll
            for (int mi = 0; mi < 2; mi++)
                LDSM4(a[mi][0], a[mi][1], a[mi][2], a[mi][3],
                      qa_addr[mi] + s*32);
            #pragma unroll
            for (int vp = 0; vp < 4; vp++)
                LDSM4(bb[vp][0], bb[vp][1], bb[vp][2], bb[vp][3],
                      kcur + kb_off[vp] + s*32);
            #pragma unroll
            for (int mi = 0; mi < 2; mi++)
                #pragma unroll
                for (int vp = 0; vp < 4; vp++) {
                    MMA_F16(sf[mi][2*vp],   a[mi], bb[vp][0], bb[vp][1]);
                    MMA_F16(sf[mi][2*vp+1], a[mi], bb[vp][2], bb[vp][3]);
                }
        }

        // Causal mask (near diagonal only)
        const int k0 = kb * 64;
        if (k0 + 63 > q0 + wid*32) {
            #pragma unroll
            for (int mi = 0; mi < 2; mi++)
                #pragma unroll
                for (int t = 0; t < 2; t++) {
                    int qg = q0 + wid*32 + mi*16 + g + t*8;
                    #pragma unroll
                    for (int j = 0; j < 8; j++) {
                        int kg = k0 + j*8 + tq*2;
                        if (kg   > qg) sf[mi][j][2*t]   = -1e30f;
                        if (kg+1 > qg) sf[mi][j][2*t+1] = -1e30f;
                    }
                }
        }

        // Softmax phase 1: row max, corr, o-scale
        float corr2[2][2], rsv[2][2];
        #pragma unroll
        for (int mi = 0; mi < 2; mi++)
            #pragma unroll
            for (int t = 0; t < 2; t++) {
                float mx = -1e30f;
                #pragma unroll
                for (int j = 0; j < 8; j++)
                    mx = fmaxf(mx, fmaxf(sf[mi][j][2*t], sf[mi][j][2*t+1]));
                mx = fmaxf(mx, __shfl_xor_sync(0xffffffffu, mx, 1));
                mx = fmaxf(mx, __shfl_xor_sync(0xffffffffu, mx, 2));
                float newm = fmaxf(m_i[mi][t], mx);
                corr2[mi][t] = __expf(m_i[mi][t] - newm);
                m_i[mi][t] = newm;
                rsv[mi][t] = 0.0f;
                #pragma unroll
                for (int j = 0; j < 8; j++) {
                    o[mi][j][2*t]   *= corr2[mi][t];
                    o[mi][j][2*t+1] *= corr2[mi][t];
                }
            }

        // exp + fp16 store of P group jj
        auto exp_store = [&](int jj) {
            #pragma unroll
            for (int mi = 0; mi < 2; mi++)
                #pragma unroll
                for (int t = 0; t < 2; t++) {
                    float p0 = __expf(sf[mi][jj][2*t]   - m_i[mi][t]);
                    float p1 = __expf(sf[mi][jj][2*t+1] - m_i[mi][t]);
                    rsv[mi][t] += p0 + p1;
                    *reinterpret_cast<__half2*>(&Ps[pbase[mi][t] + jj*8]) =
                        __floats2half2_rn(p0, p1);
                }
        };
        exp_store(0);
        exp_store(1);

        // O += P @ V, pipelined: exp/store groups 2s+2,2s+3 overlap MMA step s
        #pragma unroll
        for (int s = 0; s < 4; s++) {
            if (s < 3) { exp_store(2*s + 2); exp_store(2*s + 3); }
            __syncwarp();
            uint32_t a[2][4], bb[4][4];
            #pragma unroll
            for (int mi = 0; mi < 2; mi++)
                LDSM4(a[mi][0], a[mi][1], a[mi][2], a[mi][3],
                      pa_addr[mi] + s*32);
            #pragma unroll
            for (int vp = 0; vp < 4; vp++)
                LDSM4T(bb[vp][0], bb[vp][1], bb[vp][2], bb[vp][3],
                       vcur + vb_off[vp] + (uint32_t)s * (16*144));
            #pragma unroll
            for (int mi = 0; mi < 2; mi++)
                #pragma unroll
                for (int vp = 0; vp < 4; vp++) {
                    MMA_F16(o[mi][2*vp],   a[mi], bb[vp][0], bb[vp][1]);
                    MMA_F16(o[mi][2*vp+1], a[mi], bb[vp][2], bb[vp][3]);
                }
        }

        // Finalize l
        #pragma unroll
        for (int mi = 0; mi < 2; mi++)
            #pragma unroll
            for (int t = 0; t < 2; t++) {
                float rs = rsv[mi][t];
                rs += __shfl_xor_sync(0xffffffffu, rs, 1);
                rs += __shfl_xor_sync(0xffffffffu, rs, 2);
                l_i[mi][t] = l_i[mi][t] * corr2[mi][t] + rs;
            }
    }

    // Normalize and write fp16 to [B*L, D] (col = h*64 + d)
    const int b = bh >> 4;
    const int h = bh & 15;
    #pragma unroll
    for (int mi = 0; mi < 2; mi++)
        #pragma unroll
        for (int t = 0; t < 2; t++) {
            float inv = 1.0f / l_i[mi][t];
            int row = q0 + wid*32 + mi*16 + g + t*8;
            __half* dst = ao + ((size_t)(b * SEQ + row)) * DMODEL
                        + h * DHEAD + tq*2;
            #pragma unroll
            for (int j = 0; j < 8; j++)
                *reinterpret_cast<__half2*>(dst + j*8) =
                    __floats2half2_rn(o[mi][j][2*t] * inv,
                                      o[mi][j][2*t+1] * inv);
        }
}

// ---------------------------------------------------------------------------
extern "C" void kernel_launch(void* const* d_in, const int* in_sizes, int n_in,
                              void* d_out, int out_size)
{
    const float* x  = (const float*)d_in[0];
    const float* Wq = (const float*)d_in[1];
    const float* Wk = (const float*)d_in[2];
    const float* Wv = (const float*)d_in[3];
    const float* Wo = (const float*)d_in[4];
    float* out = (float*)d_out;

    __half *qp, *kp, *vp, *aop, *xhp, *whp;
    cudaGetSymbolAddress((void**)&qp,  g_q);
    cudaGetSymbolAddress((void**)&kp,  g_k);
    cudaGetSymbolAddress((void**)&vp,  g_v);
    cudaGetSymbolAddress((void**)&aop, g_ao);
    cudaGetSymbolAddress((void**)&xhp, g_xh);
    cudaGetSymbolAddress((void**)&whp, g_wh);

    cudaFuncSetAttribute(gemm_qkv_kernel,
        cudaFuncAttributeMaxDynamicSharedMemorySize, GEMM_SMEM_BYTES);
    cudaFuncSetAttribute(gemm_o_kernel,
        cudaFuncAttributeMaxDynamicSharedMemorySize, GEMM_SMEM_BYTES);
    cudaFuncSetAttribute(attn_f16,
        cudaFuncAttributeMaxDynamicSharedMemorySize, ATTN_SMEM_BYTES);

    round_all_kernel<<<ROUND_BLOCKS, 256>>>(x, Wq, Wk, Wv, Wo, xhp, whp);

    dim3 qkv_grid(DMODEL/128, MROWS/128, 3);   // (8, 64, 3)
    gemm_qkv_kernel<<<qkv_grid, 256, GEMM_SMEM_BYTES>>>(xhp, whp, qp, kp, vp);

    dim3 attn_grid(SEQ/128, BATCH*NHEADS);     // (16, 64)
    attn_f16<<<attn_grid, 128, ATTN_SMEM_BYTES>>>(qp, kp, vp, aop);

    dim3 o_grid(DMODEL/128, MROWS/128);        // (8, 64)
    gemm_o_kernel<<<o_grid, 256, GEMM_SMEM_BYTES>>>(aop, whp, out);
}